// round 1
// baseline (speedup 1.0000x reference)
#include <cuda_runtime.h>
#include <mma.h>

using namespace nvcuda;

// Problem constants
constexpr int Bn = 4, Tn = 256, Sn = 128, Fn = 256, Hn = 512, Vn = 1024;

// Scratch (allocation-free rule: __device__ globals)
__device__ float g_P[Bn * Tn * Hn];   // [b*T+t][h], includes b1
__device__ float g_Q[Bn * Sn * Hn];   // [b*S+s][h]

// ---------------------------------------------------------------------------
// Layer-1 projection: dst[row][h] = sum_f enc[row][f] * Wp[f][h] (+ bias[h])
// Block handles 8 rows with 256 threads; thread t covers h = t and t+256.
// ---------------------------------------------------------------------------
__device__ __forceinline__ void proj_body(const float* __restrict__ enc,
                                          const float* __restrict__ Wp,
                                          const float* __restrict__ bias,
                                          float* __restrict__ dst) {
    __shared__ float se[8][Fn];
    const int row0 = blockIdx.x * 8;
    const int tid = threadIdx.x;

    // 8 rows * 256 floats, contiguous
    for (int i = tid; i < 8 * Fn; i += 256)
        se[i >> 8][i & 255] = enc[row0 * Fn + i];
    __syncthreads();

    float acc0[8], acc1[8];
#pragma unroll
    for (int r = 0; r < 8; r++) { acc0[r] = 0.f; acc1[r] = 0.f; }

    const float* w = Wp + tid;
    for (int f = 0; f < Fn; f++) {
        float w0 = w[f * Hn];
        float w1 = w[f * Hn + 256];
#pragma unroll
        for (int r = 0; r < 8; r++) {
            acc0[r] = fmaf(se[r][f], w0, acc0[r]);
            acc1[r] = fmaf(se[r][f], w1, acc1[r]);
        }
    }

    float bias0 = bias ? bias[tid] : 0.f;
    float bias1 = bias ? bias[tid + 256] : 0.f;
#pragma unroll
    for (int r = 0; r < 8; r++) {
        dst[(row0 + r) * Hn + tid]       = acc0[r] + bias0;
        dst[(row0 + r) * Hn + tid + 256] = acc1[r] + bias1;
    }
}

__global__ void proj_P_kernel(const float* __restrict__ src,
                              const float* __restrict__ W1,
                              const float* __restrict__ b1) {
    proj_body(src, W1, b1, g_P);
}

__global__ void proj_Q_kernel(const float* __restrict__ tgt,
                              const float* __restrict__ W1) {
    proj_body(tgt, W1 + Fn * Hn, nullptr, g_Q);
}

// ---------------------------------------------------------------------------
// Main GEMM: for block (n0, bt): logits[bt*128+s][n0+n] =
//   sum_k relu(P[bt][k] + Q[b][s][k]) * W2[k][n0+n]
// BM=128 (all s of one (b,t)), BN=128, BK=32, wmma m16n16k8 tf32.
// Writes RAW logits (no b2) to out; normalize pass finishes the job.
// ---------------------------------------------------------------------------
__global__ __launch_bounds__(256, 2)
void joint_gemm(const float* __restrict__ W2, float* __restrict__ out) {
    __shared__ float As[128][36];   // [s][k] relu(P+Q), padded
    __shared__ float Bs[32][136];   // [k][n] W2 chunk, padded
    __shared__ float sP[Hn];

    const int bt  = blockIdx.y;          // b*T + t
    const int b   = bt >> 8;             // / Tn
    const int n0  = blockIdx.x * 128;
    const int tid = threadIdx.x;

    for (int i = tid; i < Hn; i += 256) sP[i] = g_P[bt * Hn + i];

    const int wid    = tid >> 5;
    const int warp_m = wid & 3;          // 0..3 -> 32-row slice
    const int warp_n = wid >> 2;         // 0..1 -> 64-col slice

    wmma::fragment<wmma::accumulator, 16, 16, 8, float> acc[2][4];
#pragma unroll
    for (int i = 0; i < 2; i++)
#pragma unroll
        for (int j = 0; j < 4; j++)
            wmma::fill_fragment(acc[i][j], 0.f);

    const float* Qbase = g_Q + b * Sn * Hn;   // [128][512]

    for (int k0 = 0; k0 < Hn; k0 += 32) {
        __syncthreads();   // first iter: sP ready; later: smem safe to overwrite

        // A tile: relu(P + Q), 128x32, float4 granularity
#pragma unroll
        for (int j = 0; j < 4; j++) {
            int p  = tid + 256 * j;        // float4 index, [0,1024)
            int s  = p >> 3;
            int k4 = (p & 7) * 4;
            float4 q = *(const float4*)(Qbase + s * Hn + k0 + k4);
            float4 a;
            a.x = fmaxf(q.x + sP[k0 + k4 + 0], 0.f);
            a.y = fmaxf(q.y + sP[k0 + k4 + 1], 0.f);
            a.z = fmaxf(q.z + sP[k0 + k4 + 2], 0.f);
            a.w = fmaxf(q.w + sP[k0 + k4 + 3], 0.f);
            *(float4*)&As[s][k4] = a;
        }
        // B tile: W2 chunk 32x128
#pragma unroll
        for (int j = 0; j < 4; j++) {
            int p  = tid + 256 * j;        // float4 index
            int k  = p >> 5;
            int n4 = (p & 31) * 4;
            *(float4*)&Bs[k][n4] =
                *(const float4*)(W2 + (size_t)(k0 + k) * Vn + n0 + n4);
        }
        __syncthreads();

#pragma unroll
        for (int kk = 0; kk < 32; kk += 8) {
            wmma::fragment<wmma::matrix_a, 16, 16, 8, wmma::precision::tf32,
                           wmma::row_major> af[2];
            wmma::fragment<wmma::matrix_b, 16, 16, 8, wmma::precision::tf32,
                           wmma::row_major> bf[4];
#pragma unroll
            for (int i = 0; i < 2; i++) {
                wmma::load_matrix_sync(af[i], &As[warp_m * 32 + 16 * i][kk], 36);
#pragma unroll
                for (int e = 0; e < af[i].num_elements; e++)
                    af[i].x[e] = wmma::__float_to_tf32(af[i].x[e]);
            }
#pragma unroll
            for (int j = 0; j < 4; j++) {
                wmma::load_matrix_sync(bf[j], &Bs[kk][warp_n * 64 + 16 * j], 136);
#pragma unroll
                for (int e = 0; e < bf[j].num_elements; e++)
                    bf[j].x[e] = wmma::__float_to_tf32(bf[j].x[e]);
            }
#pragma unroll
            for (int i = 0; i < 2; i++)
#pragma unroll
                for (int j = 0; j < 4; j++)
                    wmma::mma_sync(acc[i][j], af[i], bf[j], acc[i][j]);
        }
    }

    // Epilogue: raw logits straight to gmem (row-major, ld = V)
    const size_t rowbase = (size_t)bt * Sn;
#pragma unroll
    for (int i = 0; i < 2; i++) {
        int rg = warp_m * 32 + 16 * i;
#pragma unroll
        for (int j = 0; j < 4; j++) {
            int cg = n0 + warp_n * 64 + 16 * j;
            wmma::store_matrix_sync(out + (rowbase + rg) * Vn + cg, acc[i][j],
                                    Vn, wmma::mem_row_major);
        }
    }
}

// ---------------------------------------------------------------------------
// In-place log_softmax with b2 add: one warp per row (V=1024 = 32 lanes x 8
// float4, fully register-resident).
// ---------------------------------------------------------------------------
__global__ __launch_bounds__(256)
void lsm_kernel(float* __restrict__ out, const float* __restrict__ b2) {
    const int row  = blockIdx.x * 8 + (threadIdx.x >> 5);
    const int lane = threadIdx.x & 31;

    float4* p = (float4*)(out + (size_t)row * Vn);
    const float4* pb = (const float4*)b2;

    float4 v[8];
    float mx = -1e30f;
#pragma unroll
    for (int i = 0; i < 8; i++) {
        float4 x  = p[lane + 32 * i];
        float4 bb = __ldg(&pb[lane + 32 * i]);
        x.x += bb.x; x.y += bb.y; x.z += bb.z; x.w += bb.w;
        v[i] = x;
        mx = fmaxf(mx, fmaxf(fmaxf(x.x, x.y), fmaxf(x.z, x.w)));
    }
#pragma unroll
    for (int o = 16; o > 0; o >>= 1)
        mx = fmaxf(mx, __shfl_xor_sync(0xffffffffu, mx, o));

    float sum = 0.f;
#pragma unroll
    for (int i = 0; i < 8; i++) {
        sum += __expf(v[i].x - mx) + __expf(v[i].y - mx) +
               __expf(v[i].z - mx) + __expf(v[i].w - mx);
    }
#pragma unroll
    for (int o = 16; o > 0; o >>= 1)
        sum += __shfl_xor_sync(0xffffffffu, sum, o);

    const float lse = mx + logf(sum);
#pragma unroll
    for (int i = 0; i < 8; i++) {
        float4 x = v[i];
        x.x -= lse; x.y -= lse; x.z -= lse; x.w -= lse;
        p[lane + 32 * i] = x;
    }
}

// ---------------------------------------------------------------------------
extern "C" void kernel_launch(void* const* d_in, const int* in_sizes, int n_in,
                              void* d_out, int out_size) {
    const float* src = (const float*)d_in[0];  // [B,T,F]
    const float* tgt = (const float*)d_in[1];  // [B,S,F]
    const float* W1  = (const float*)d_in[2];  // [2F,H]
    const float* b1  = (const float*)d_in[3];  // [H]
    const float* W2  = (const float*)d_in[4];  // [H,V]
    const float* b2  = (const float*)d_in[5];  // [V]
    float* out = (float*)d_out;                // [B,T,S,V]

    (void)in_sizes; (void)n_in; (void)out_size;

    proj_P_kernel<<<(Bn * Tn) / 8, 256>>>(src, W1, b1);
    proj_Q_kernel<<<(Bn * Sn) / 8, 256>>>(tgt, W1);

    dim3 grid(Vn / 128, Bn * Tn);
    joint_gemm<<<grid, 256>>>(W2, out);

    lsm_kernel<<<(Bn * Tn * Sn) / 8, 256>>>(out, b2);
}

// round 2
// speedup vs baseline: 1.7649x; 1.7649x over previous
#include <cuda_runtime.h>
#include <cstdint>

// Problem constants
constexpr int Bn = 4, Tn = 256, Sn = 128, Fn = 256, Hn = 512, Vn = 1024;

// Scratch (allocation-free rule: __device__ globals)
__device__ float g_P[Bn * Tn * Hn];     // [b*T+t][h], includes b1
__device__ float g_Q[Bn * Sn * Hn];     // [b*S+s][h]
__device__ float g_W2r[Hn * Vn];        // W2 pre-rounded to tf32

// ---------------------------------------------------------------------------
// helpers
// ---------------------------------------------------------------------------
__device__ __forceinline__ uint32_t f2tf32(float x) {
    uint32_t r;
    asm("cvt.rna.tf32.f32 %0, %1;" : "=r"(r) : "f"(x));
    return r;
}

__device__ __forceinline__ void cp_async16(void* smem_dst, const void* gmem_src) {
    uint32_t s;
    asm("{ .reg .u64 t; cvta.to.shared.u64 t, %1; cvt.u32.u64 %0, t; }"
        : "=r"(s) : "l"(smem_dst));
    asm volatile("cp.async.cg.shared.global [%0], [%1], 16;" :: "r"(s), "l"(gmem_src));
}

__device__ __forceinline__ void cp_commit() {
    asm volatile("cp.async.commit_group;");
}

template <int N>
__device__ __forceinline__ void cp_wait() {
    asm volatile("cp.async.wait_group %0;" :: "n"(N));
}

__device__ __forceinline__ void mma_tf32(float (&c)[4], const uint32_t (&a)[4],
                                         const uint32_t (&b)[2]) {
    asm volatile(
        "mma.sync.aligned.m16n8k8.row.col.f32.tf32.tf32.f32 "
        "{%0,%1,%2,%3}, {%4,%5,%6,%7}, {%8,%9}, {%0,%1,%2,%3};"
        : "+f"(c[0]), "+f"(c[1]), "+f"(c[2]), "+f"(c[3])
        : "r"(a[0]), "r"(a[1]), "r"(a[2]), "r"(a[3]), "r"(b[0]), "r"(b[1]));
}

// ---------------------------------------------------------------------------
// W2 -> tf32-rounded copy (one-time per call; 2MB, trivial)
// ---------------------------------------------------------------------------
__global__ void round_w2_kernel(const float* __restrict__ W2) {
    int i = (blockIdx.x * 256 + threadIdx.x) * 4;
    float4 v = *(const float4*)(W2 + i);
    uint4 r;
    r.x = f2tf32(v.x); r.y = f2tf32(v.y); r.z = f2tf32(v.z); r.w = f2tf32(v.w);
    *(uint4*)(g_W2r + i) = r;
}

// ---------------------------------------------------------------------------
// Layer-1 projection: dst[row][h] = sum_f enc[row][f] * Wp[f][h] (+ bias[h])
// ---------------------------------------------------------------------------
__device__ __forceinline__ void proj_body(const float* __restrict__ enc,
                                          const float* __restrict__ Wp,
                                          const float* __restrict__ bias,
                                          float* __restrict__ dst) {
    __shared__ float se[8][Fn];
    const int row0 = blockIdx.x * 8;
    const int tid = threadIdx.x;

    for (int i = tid; i < 8 * Fn; i += 256)
        se[i >> 8][i & 255] = enc[row0 * Fn + i];
    __syncthreads();

    float acc0[8], acc1[8];
#pragma unroll
    for (int r = 0; r < 8; r++) { acc0[r] = 0.f; acc1[r] = 0.f; }

    const float* w = Wp + tid;
    for (int f = 0; f < Fn; f++) {
        float w0 = w[f * Hn];
        float w1 = w[f * Hn + 256];
#pragma unroll
        for (int r = 0; r < 8; r++) {
            acc0[r] = fmaf(se[r][f], w0, acc0[r]);
            acc1[r] = fmaf(se[r][f], w1, acc1[r]);
        }
    }

    float bias0 = bias ? bias[tid] : 0.f;
    float bias1 = bias ? bias[tid + 256] : 0.f;
#pragma unroll
    for (int r = 0; r < 8; r++) {
        dst[(row0 + r) * Hn + tid]       = acc0[r] + bias0;
        dst[(row0 + r) * Hn + tid + 256] = acc1[r] + bias1;
    }
}

__global__ void proj_P_kernel(const float* __restrict__ src,
                              const float* __restrict__ W1,
                              const float* __restrict__ b1) {
    proj_body(src, W1, b1, g_P);
}

__global__ void proj_Q_kernel(const float* __restrict__ tgt,
                              const float* __restrict__ W1) {
    proj_body(tgt, W1 + Fn * Hn, nullptr, g_Q);
}

// ---------------------------------------------------------------------------
// Main GEMM: logits[bt*128+s][n0+n] = sum_k relu(P[bt][k]+Q[b][s][k]) * W2[k][n]
// BM=128 BN=128 BK=32, mma.m16n8k8 tf32, 2-stage cp.async double buffer.
// Warp layout 4x2: warp tile 32 rows x 64 cols.
// ---------------------------------------------------------------------------
constexpr int QLD = 36;    // Qs row pitch (floats): bank = 4g+q, conflict-free
constexpr int BLD = 132;   // Bs row pitch (floats): bank = 4q+g, conflict-free
constexpr int QS_FLOATS = 2 * 128 * QLD;          // 9216
constexpr int BS_FLOATS = 2 * 32 * BLD;           // 8448
constexpr int SMEM_FLOATS = QS_FLOATS + BS_FLOATS + Hn;   // + sP
constexpr int SMEM_BYTES = SMEM_FLOATS * 4;       // 72704

__global__ __launch_bounds__(256, 2)
void joint_gemm(const float* __restrict__ dummy, float* __restrict__ out) {
    extern __shared__ float sm[];
    float* Qs = sm;                       // [2][128][QLD]
    float* Bs = sm + QS_FLOATS;           // [2][32][BLD]
    float* sP = sm + QS_FLOATS + BS_FLOATS;

    const int bt  = blockIdx.y;           // b*T + t
    const int b   = bt >> 8;
    const int n0  = blockIdx.x * 128;
    const int tid = threadIdx.x;
    const int lane = tid & 31;
    const int wid  = tid >> 5;
    const int warp_m = wid & 3;           // 32-row slice
    const int warp_n = wid >> 2;          // 64-col slice
    const int q = lane & 3;
    const int g = lane >> 2;

    const float* Qg = g_Q + (size_t)b * Sn * Hn;
    const float* Wg = g_W2r;

    // ---- stage issue helper (BK=32 tile of Q and W2) ----
    auto issue_stage = [&](int buf, int k0) {
        float* qdst = Qs + buf * 128 * QLD;
        float* bdst = Bs + buf * 32 * BLD;
#pragma unroll
        for (int r = 0; r < 4; r++) {
            int c = r * 256 + tid;        // Q: 1024 chunks of 16B
            int s = c >> 3, ch = (c & 7) * 4;
            cp_async16(qdst + s * QLD + ch, Qg + (size_t)s * Hn + k0 + ch);
        }
#pragma unroll
        for (int r = 0; r < 4; r++) {
            int c = r * 256 + tid;        // B: 1024 chunks of 16B
            int k = c >> 5, ch = (c & 31) * 4;
            cp_async16(bdst + k * BLD + ch, Wg + (size_t)(k0 + k) * Vn + n0 + ch);
        }
        cp_commit();
    };

    issue_stage(0, 0);

    // sP: this block's P row (overlaps with stage-0 cp.async flight)
    for (int i = tid; i < Hn; i += 256) sP[i] = g_P[(size_t)bt * Hn + i];

    float acc[2][8][4];
#pragma unroll
    for (int i = 0; i < 2; i++)
#pragma unroll
        for (int j = 0; j < 8; j++)
#pragma unroll
            for (int e = 0; e < 4; e++) acc[i][j][e] = 0.f;

    constexpr int NIT = Hn / 32;          // 16
    for (int it = 0; it < NIT; it++) {
        if (it + 1 < NIT) {
            issue_stage((it + 1) & 1, (it + 1) * 32);
            cp_wait<1>();
        } else {
            cp_wait<0>();
        }
        __syncthreads();

        const float* qb = Qs + (it & 1) * 128 * QLD;
        const float* bb = Bs + (it & 1) * 32 * BLD;
        const int k0 = it * 32;

#pragma unroll
        for (int kk = 0; kk < 32; kk += 8) {
            float p0 = sP[k0 + kk + q];
            float p1 = sP[k0 + kk + q + 4];

            uint32_t afr[2][4];
#pragma unroll
            for (int i = 0; i < 2; i++) {
                int s0 = warp_m * 32 + 16 * i + g;
                afr[i][0] = f2tf32(fmaxf(qb[s0 * QLD + kk + q] + p0, 0.f));
                afr[i][1] = f2tf32(fmaxf(qb[(s0 + 8) * QLD + kk + q] + p0, 0.f));
                afr[i][2] = f2tf32(fmaxf(qb[s0 * QLD + kk + q + 4] + p1, 0.f));
                afr[i][3] = f2tf32(fmaxf(qb[(s0 + 8) * QLD + kk + q + 4] + p1, 0.f));
            }
#pragma unroll
            for (int j = 0; j < 8; j++) {
                uint32_t bfr[2];
                int n = warp_n * 64 + 8 * j + g;
                bfr[0] = __float_as_uint(bb[(kk + q) * BLD + n]);
                bfr[1] = __float_as_uint(bb[(kk + q + 4) * BLD + n]);
                mma_tf32(acc[0][j], afr[0], bfr);
                mma_tf32(acc[1][j], afr[1], bfr);
            }
        }
        __syncthreads();
    }

    // Epilogue: raw logits to gmem. c0,c1 -> (row, 2q..2q+1); c2,c3 -> row+8.
    const size_t rowbase = (size_t)bt * Sn;
#pragma unroll
    for (int i = 0; i < 2; i++) {
        int r0 = warp_m * 32 + 16 * i + g;
#pragma unroll
        for (int j = 0; j < 8; j++) {
            int col = n0 + warp_n * 64 + 8 * j + 2 * q;
            float2 v0 = make_float2(acc[i][j][0], acc[i][j][1]);
            float2 v1 = make_float2(acc[i][j][2], acc[i][j][3]);
            *(float2*)(out + (rowbase + r0) * Vn + col) = v0;
            *(float2*)(out + (rowbase + r0 + 8) * Vn + col) = v1;
        }
    }
    (void)dummy;
}

// ---------------------------------------------------------------------------
// In-place log_softmax with b2 add: one warp per row.
// ---------------------------------------------------------------------------
__global__ __launch_bounds__(256)
void lsm_kernel(float* __restrict__ out, const float* __restrict__ b2) {
    const int row  = blockIdx.x * 8 + (threadIdx.x >> 5);
    const int lane = threadIdx.x & 31;

    float4* p = (float4*)(out + (size_t)row * Vn);
    const float4* pb = (const float4*)b2;

    float4 v[8];
    float mx = -1e30f;
#pragma unroll
    for (int i = 0; i < 8; i++) {
        float4 x  = p[lane + 32 * i];
        float4 bb = __ldg(&pb[lane + 32 * i]);
        x.x += bb.x; x.y += bb.y; x.z += bb.z; x.w += bb.w;
        v[i] = x;
        mx = fmaxf(mx, fmaxf(fmaxf(x.x, x.y), fmaxf(x.z, x.w)));
    }
#pragma unroll
    for (int o = 16; o > 0; o >>= 1)
        mx = fmaxf(mx, __shfl_xor_sync(0xffffffffu, mx, o));

    float sum = 0.f;
#pragma unroll
    for (int i = 0; i < 8; i++) {
        sum += __expf(v[i].x - mx) + __expf(v[i].y - mx) +
               __expf(v[i].z - mx) + __expf(v[i].w - mx);
    }
#pragma unroll
    for (int o = 16; o > 0; o >>= 1)
        sum += __shfl_xor_sync(0xffffffffu, sum, o);

    const float lse = mx + logf(sum);
#pragma unroll
    for (int i = 0; i < 8; i++) {
        float4 x = v[i];
        x.x -= lse; x.y -= lse; x.z -= lse; x.w -= lse;
        p[lane + 32 * i] = x;
    }
}

// ---------------------------------------------------------------------------
extern "C" void kernel_launch(void* const* d_in, const int* in_sizes, int n_in,
                              void* d_out, int out_size) {
    const float* src = (const float*)d_in[0];  // [B,T,F]
    const float* tgt = (const float*)d_in[1];  // [B,S,F]
    const float* W1  = (const float*)d_in[2];  // [2F,H]
    const float* b1  = (const float*)d_in[3];  // [H]
    const float* W2  = (const float*)d_in[4];  // [H,V]
    const float* b2  = (const float*)d_in[5];  // [V]
    float* out = (float*)d_out;                // [B,T,S,V]

    (void)in_sizes; (void)n_in; (void)out_size;

    static bool attr_set = false;
    if (!attr_set) {
        cudaFuncSetAttribute(joint_gemm,
                             cudaFuncAttributeMaxDynamicSharedMemorySize,
                             SMEM_BYTES);
        attr_set = true;
    }

    round_w2_kernel<<<(Hn * Vn) / (256 * 4), 256>>>(W2);
    proj_P_kernel<<<(Bn * Tn) / 8, 256>>>(src, W1, b1);
    proj_Q_kernel<<<(Bn * Sn) / 8, 256>>>(tgt, W1);

    dim3 grid(Vn / 128, Bn * Tn);
    joint_gemm<<<grid, 256, SMEM_BYTES>>>(nullptr, out);

    lsm_kernel<<<(Bn * Tn * Sn) / 8, 256>>>(out, b2);
}

// round 6
// speedup vs baseline: 3.2070x; 1.8172x over previous
#include <cuda_runtime.h>
#include <cuda_bf16.h>
#include <cstdint>

// Problem constants
constexpr int Bn = 4, Tn = 256, Sn = 128, Fn = 256, Hn = 512, Vn = 1024;

// Scratch (allocation-free rule: __device__ globals)
__device__ float g_P[Bn * Tn * Hn];       // [b*T+t][h], includes b1
__device__ float g_Q[Bn * Sn * Hn];       // [b*S+s][h]
// W2 in bf16 fragment order: [ck(16)][ntile(8)][wn(2)][j(8)][kki(2)][lane(32)] uint2
__device__ uint2 g_W2f[16 * 8 * 1024];

// ---------------------------------------------------------------------------
// helpers
// ---------------------------------------------------------------------------
__device__ __forceinline__ uint32_t packbf(float lo, float hi) {
    __nv_bfloat162 h = __floats2bfloat162_rn(lo, hi);   // lo -> low 16 bits
    return *reinterpret_cast<uint32_t*>(&h);
}

__device__ __forceinline__ uint32_t smem_u32(const void* p) {
    uint32_t a;
    asm("{ .reg .u64 t; cvta.to.shared.u64 t, %1; cvt.u32.u64 %0, t; }"
        : "=r"(a) : "l"(p));
    return a;
}

__device__ __forceinline__ void cp16(uint32_t smem_dst, const void* gmem_src) {
    asm volatile("cp.async.cg.shared.global [%0], [%1], 16;"
                 :: "r"(smem_dst), "l"(gmem_src));
}
__device__ __forceinline__ void cp_commit() {
    asm volatile("cp.async.commit_group;");
}
template <int N>
__device__ __forceinline__ void cp_wait() {
    asm volatile("cp.async.wait_group %0;" :: "n"(N));
}

__device__ __forceinline__ void mma_bf16(float (&c)[4], const uint32_t (&a)[4],
                                         uint32_t b0, uint32_t b1) {
    asm volatile(
        "mma.sync.aligned.m16n8k16.row.col.f32.bf16.bf16.f32 "
        "{%0,%1,%2,%3}, {%4,%5,%6,%7}, {%8,%9}, {%0,%1,%2,%3};"
        : "+f"(c[0]), "+f"(c[1]), "+f"(c[2]), "+f"(c[3])
        : "r"(a[0]), "r"(a[1]), "r"(a[2]), "r"(a[3]), "r"(b0), "r"(b1));
}

// ---------------------------------------------------------------------------
// W2 [H][V] f32 -> g_W2f bf16 fragment order (one-time, 1MB out).
// Fragment (m16n8k16, B col-major): b0={B[kb+2q][n],B[kb+2q+1][n]},
//                                   b1={B[kb+2q+8][n],B[kb+2q+9][n]}
// ---------------------------------------------------------------------------
__global__ void w2frag_kernel(const float* __restrict__ W2) {
    const int n  = blockIdx.x * 256 + threadIdx.x;   // 0..1023
    const int ck = blockIdx.y;                       // 0..15 (32-K chunk)
    const int nt = n >> 7, wn = (n >> 6) & 1, j = (n >> 3) & 7, g = n & 7;
    uint2* dst = g_W2f + (size_t)(ck * 8 + nt) * 1024 + (wn * 8 + j) * 2 * 32;
#pragma unroll
    for (int kki = 0; kki < 2; kki++) {
#pragma unroll
        for (int q = 0; q < 4; q++) {
            int k = ck * 32 + kki * 16 + 2 * q;
            uint2 v;
            v.x = packbf(W2[(size_t)k * Vn + n], W2[(size_t)(k + 1) * Vn + n]);
            v.y = packbf(W2[(size_t)(k + 8) * Vn + n], W2[(size_t)(k + 9) * Vn + n]);
            dst[kki * 32 + 4 * g + q] = v;
        }
    }
}

// ---------------------------------------------------------------------------
// Layer-1 projection, split over (row-tile 8, h-tile 128): 768 blocks.
// ---------------------------------------------------------------------------
__global__ __launch_bounds__(256)
void proj_kernel(const float* __restrict__ src, const float* __restrict__ tgt,
                 const float* __restrict__ W1, const float* __restrict__ b1) {
    __shared__ float se[8][Fn];
    const int rt = blockIdx.x;
    const bool isP = rt < 128;
    const float* enc = isP ? src : tgt;
    float* dst = isP ? g_P : g_Q;
    const float* Wp = isP ? W1 : (W1 + Fn * Hn);
    const int row0 = (isP ? rt : rt - 128) * 8;

    const int tid = threadIdx.x;
    for (int i = tid; i < 8 * Fn; i += 256)
        se[i >> 8][i & 255] = enc[(size_t)row0 * Fn + i];
    __syncthreads();

    const int h  = blockIdx.y * 128 + (tid & 127);
    const int rh = tid >> 7;               // 0..1 -> 4-row half

    float acc[4] = {0.f, 0.f, 0.f, 0.f};
    const float* w = Wp + h;
    for (int f = 0; f < Fn; f++) {
        float wv = w[(size_t)f * Hn];
#pragma unroll
        for (int r = 0; r < 4; r++)
            acc[r] = fmaf(se[rh * 4 + r][f], wv, acc[r]);
    }
    const float bias = isP ? b1[h] : 0.f;
#pragma unroll
    for (int r = 0; r < 4; r++)
        dst[(size_t)(row0 + rh * 4 + r) * Hn + h] = acc[r] + bias;
}

// ---------------------------------------------------------------------------
// Main GEMM: logits[bt*128+s][n0+n] = sum_k relu(P[bt][k]+Q[b][s][k])*W2[k][n]
// BM=128 BN=128 BK=32, mma.m16n8k16 bf16, fragment-order smem operands.
// 8 warps 4x2 (warp tile 32x64). A built in fragment layout from gmem Q + sP.
// ---------------------------------------------------------------------------
constexpr int A_ENTRY = 528;                  // 512B fragment block + 16B pad

__global__ __launch_bounds__(256, 2)
void joint_gemm(float* __restrict__ out) {
    __shared__ char  As[2][16 * A_ENTRY];     // [buf][(wm*2+i)*2+kki] blocks
    __shared__ uint2 Bs[3][1024];             // [buf][wn][j][kki][lane]
    __shared__ float sP[Hn];

    const int bt  = blockIdx.y;               // b*T + t
    const int b   = bt >> 8;
    const int nt  = blockIdx.x;               // n-tile, n0 = nt*128
    const int tid = threadIdx.x;
    const int wid = tid >> 5;
    const int lane = tid & 31;

    const float* Qg = g_Q + (size_t)b * Sn * Hn;

    // builder decode: tid = wm[7:6] i[5] g[4:2] kki[1] qh[0]
    const int bm_wm = tid >> 6, bm_i = (tid >> 5) & 1;
    const int bm_g = (tid >> 2) & 7, bm_kki = (tid >> 1) & 1, bm_qh = tid & 1;
    const int bm_entry = ((bm_wm * 2 + bm_i) * 2 + bm_kki);
    const int bm_lt = 4 * bm_g + 2 * bm_qh;   // fragment lanes lt, lt+1
    const int s_lo = bm_wm * 32 + bm_i * 16 + bm_g;
    const int ka_  = bm_kki * 16 + bm_qh * 4; // k offset within 32-chunk
    const float* qlo_base = Qg + (size_t)s_lo * Hn + ka_;
    const float* qhi_base = qlo_base + 8 * Hn;

    float4 qv0, qv1, qv2, qv3;                // Q regs for next build
    auto ldq = [&](int k0n) {
        qv0 = *(const float4*)(qlo_base + k0n);
        qv1 = *(const float4*)(qlo_base + k0n + 8);
        qv2 = *(const float4*)(qhi_base + k0n);
        qv3 = *(const float4*)(qhi_base + k0n + 8);
    };

    auto buildA = [&](int buf, int k0n) {
        float4 pa = *(const float4*)(sP + k0n + ka_);
        float4 pb = *(const float4*)(sP + k0n + ka_ + 8);
        uint4* rowp = (uint4*)(As[buf] + bm_entry * A_ENTRY);
        uint4 u0, u1;
        u0.x = packbf(fmaxf(qv0.x + pa.x, 0.f), fmaxf(qv0.y + pa.y, 0.f));
        u0.y = packbf(fmaxf(qv2.x + pa.x, 0.f), fmaxf(qv2.y + pa.y, 0.f));
        u0.z = packbf(fmaxf(qv1.x + pb.x, 0.f), fmaxf(qv1.y + pb.y, 0.f));
        u0.w = packbf(fmaxf(qv3.x + pb.x, 0.f), fmaxf(qv3.y + pb.y, 0.f));
        u1.x = packbf(fmaxf(qv0.z + pa.z, 0.f), fmaxf(qv0.w + pa.w, 0.f));
        u1.y = packbf(fmaxf(qv2.z + pa.z, 0.f), fmaxf(qv2.w + pa.w, 0.f));
        u1.z = packbf(fmaxf(qv1.z + pb.z, 0.f), fmaxf(qv1.w + pb.w, 0.f));
        u1.w = packbf(fmaxf(qv3.z + pb.z, 0.f), fmaxf(qv3.w + pb.w, 0.f));
        rowp[bm_lt]     = u0;
        rowp[bm_lt + 1] = u1;
    };

    auto stageB = [&](int ck, int buf) {
        const char* src = (const char*)g_W2f + (size_t)(ck * 8 + nt) * 8192;
        uint32_t dst = smem_u32(Bs[buf]);
#pragma unroll
        for (int r = 0; r < 2; r++) {
            int c = tid + 256 * r;            // 512 chunks of 16B
            cp16(dst + c * 16, src + c * 16);
        }
    };

    // ---- prologue ----
    stageB(0, 0); cp_commit();
    stageB(1, 1); cp_commit();
    if (tid < 128)
        ((float4*)sP)[tid] = *((const float4*)(g_P + (size_t)bt * Hn) + tid);
    __syncthreads();                          // sP visible for builds

    ldq(0);
    buildA(0, 0);                             // A(0) into buf 0
    ldq(32);                                  // Q for A(1), in flight

    float acc[2][8][4];
#pragma unroll
    for (int i = 0; i < 2; i++)
#pragma unroll
        for (int j = 0; j < 8; j++)
#pragma unroll
            for (int e = 0; e < 4; e++) acc[i][j][e] = 0.f;

    const int wm = wid & 3;                   // 32-row slice
    const int wn = wid >> 2;                  // 64-col slice

    // ---- main loop ----
    for (int it = 0; it < 16; it++) {
        cp_wait<1>();                         // B(it) arrived
        __syncthreads();                      // A(it) stores + B(it) visible

        const char*  Ab = As[it & 1];
        const uint2* Bb = Bs[it % 3] + (wn * 8) * 2 * 32;

#pragma unroll
        for (int kki = 0; kki < 2; kki++) {
            uint32_t a0[4], a1[4];
            *(uint4*)a0 = ((const uint4*)(Ab + ((wm * 2 + 0) * 2 + kki) * A_ENTRY))[lane];
            *(uint4*)a1 = ((const uint4*)(Ab + ((wm * 2 + 1) * 2 + kki) * A_ENTRY))[lane];
#pragma unroll
            for (int j = 0; j < 8; j++) {
                uint2 bv = Bb[(j * 2 + kki) * 32 + lane];
                mma_bf16(acc[0][j], a0, bv.x, bv.y);
                mma_bf16(acc[1][j], a1, bv.x, bv.y);
            }
        }

        // tail: prepare iter it+1 / it+2 (overlaps with other warps' MMA)
        if (it < 15) buildA((it + 1) & 1, (it + 1) * 32);
        if (it < 14) {
            ldq((it + 2) * 32);
            stageB(it + 2, (it + 2) % 3);
        }
        cp_commit();                          // empty group ok; keeps accounting
    }

    // ---- epilogue: raw logits to gmem ----
    const int gg = lane >> 2, tq = lane & 3;
    const size_t rowbase = (size_t)bt * Sn;
#pragma unroll
    for (int i = 0; i < 2; i++) {
        int r0 = wm * 32 + i * 16 + gg;
#pragma unroll
        for (int j = 0; j < 8; j++) {
            int col = nt * 128 + wn * 64 + 8 * j + 2 * tq;
            *(float2*)(out + (rowbase + r0) * Vn + col) =
                make_float2(acc[i][j][0], acc[i][j][1]);
            *(float2*)(out + (rowbase + r0 + 8) * Vn + col) =
                make_float2(acc[i][j][2], acc[i][j][3]);
        }
    }
}

// ---------------------------------------------------------------------------
// In-place log_softmax with b2 add: one warp per row.
// ---------------------------------------------------------------------------
__global__ __launch_bounds__(256)
void lsm_kernel(float* __restrict__ out, const float* __restrict__ b2) {
    const int row  = blockIdx.x * 8 + (threadIdx.x >> 5);
    const int lane = threadIdx.x & 31;

    float4* p = (float4*)(out + (size_t)row * Vn);
    const float4* pb = (const float4*)b2;

    float4 v[8];
    float mx = -1e30f;
#pragma unroll
    for (int i = 0; i < 8; i++) {
        float4 x  = p[lane + 32 * i];
        float4 bb = __ldg(&pb[lane + 32 * i]);
        x.x += bb.x; x.y += bb.y; x.z += bb.z; x.w += bb.w;
        v[i] = x;
        mx = fmaxf(mx, fmaxf(fmaxf(x.x, x.y), fmaxf(x.z, x.w)));
    }
#pragma unroll
    for (int o = 16; o > 0; o >>= 1)
        mx = fmaxf(mx, __shfl_xor_sync(0xffffffffu, mx, o));

    float sum = 0.f;
#pragma unroll
    for (int i = 0; i < 8; i++) {
        sum += __expf(v[i].x - mx) + __expf(v[i].y - mx) +
               __expf(v[i].z - mx) + __expf(v[i].w - mx);
    }
#pragma unroll
    for (int o = 16; o > 0; o >>= 1)
        sum += __shfl_xor_sync(0xffffffffu, sum, o);

    const float lse = mx + logf(sum);
#pragma unroll
    for (int i = 0; i < 8; i++) {
        float4 x = v[i];
        x.x -= lse; x.y -= lse; x.z -= lse; x.w -= lse;
        p[lane + 32 * i] = x;
    }
}

// ---------------------------------------------------------------------------
extern "C" void kernel_launch(void* const* d_in, const int* in_sizes, int n_in,
                              void* d_out, int out_size) {
    const float* src = (const float*)d_in[0];  // [B,T,F]
    const float* tgt = (const float*)d_in[1];  // [B,S,F]
    const float* W1  = (const float*)d_in[2];  // [2F,H]
    const float* b1  = (const float*)d_in[3];  // [H]
    const float* W2  = (const float*)d_in[4];  // [H,V]
    const float* b2  = (const float*)d_in[5];  // [V]
    float* out = (float*)d_out;                // [B,T,S,V]

    (void)in_sizes; (void)n_in; (void)out_size;

    w2frag_kernel<<<dim3(4, 16), 256>>>(W2);
    proj_kernel<<<dim3(192, 4), 256>>>(src, tgt, W1, b1);

    joint_gemm<<<dim3(Vn / 128, Bn * Tn), 256>>>(out);

    lsm_kernel<<<(Bn * Tn * Sn) / 8, 256>>>(out, b2);
}

// round 7
// speedup vs baseline: 3.2605x; 1.0167x over previous
#include <cuda_runtime.h>
#include <cuda_bf16.h>
#include <cuda_fp16.h>
#include <cstdint>

// Problem constants
constexpr int Bn = 4, Tn = 256, Sn = 128, Fn = 256, Hn = 512, Vn = 1024;

// Scratch (allocation-free rule: __device__ globals)
__device__ float g_P[Bn * Tn * Hn];       // [b*T+t][h], includes b1
__device__ float g_Q[Bn * Sn * Hn];       // [b*S+s][h]
// W2 bf16 fragment order: [ck(16)][ntile(8)] x 512 uint4:
//   index (wn*8+j)*32 + lane, uint4 = {kki0.b0, kki0.b1, kki1.b0, kki1.b1}
__device__ uint4 g_W2f[16 * 8 * 512];
// fp16 raw logits scratch (256 MB)
__device__ __half g_L[(size_t)Bn * Tn * Sn * Vn];

// ---------------------------------------------------------------------------
// helpers
// ---------------------------------------------------------------------------
__device__ __forceinline__ uint32_t packbf(float lo, float hi) {
    __nv_bfloat162 h = __floats2bfloat162_rn(lo, hi);   // lo -> low 16 bits
    return *reinterpret_cast<uint32_t*>(&h);
}

__device__ __forceinline__ uint32_t smem_u32(const void* p) {
    uint32_t a;
    asm("{ .reg .u64 t; cvta.to.shared.u64 t, %1; cvt.u32.u64 %0, t; }"
        : "=r"(a) : "l"(p));
    return a;
}

__device__ __forceinline__ void cp16(uint32_t smem_dst, const void* gmem_src) {
    asm volatile("cp.async.cg.shared.global [%0], [%1], 16;"
                 :: "r"(smem_dst), "l"(gmem_src));
}
__device__ __forceinline__ void cp_commit() {
    asm volatile("cp.async.commit_group;");
}
template <int N>
__device__ __forceinline__ void cp_wait() {
    asm volatile("cp.async.wait_group %0;" :: "n"(N));
}

__device__ __forceinline__ void mma_bf16(float (&c)[4], const uint32_t (&a)[4],
                                         uint32_t b0, uint32_t b1) {
    asm volatile(
        "mma.sync.aligned.m16n8k16.row.col.f32.bf16.bf16.f32 "
        "{%0,%1,%2,%3}, {%4,%5,%6,%7}, {%8,%9}, {%0,%1,%2,%3};"
        : "+f"(c[0]), "+f"(c[1]), "+f"(c[2]), "+f"(c[3])
        : "r"(a[0]), "r"(a[1]), "r"(a[2]), "r"(a[3]), "r"(b0), "r"(b1));
}

// ---------------------------------------------------------------------------
// W2 [H][V] f32 -> g_W2f bf16 fragment order (one-time, 1MB out).
// m16n8k16 B col-major fragment: lane l -> col n = l>>2, q = l&3;
//   b0 = {B[kb+2q][n], B[kb+2q+1][n]}, b1 = {B[kb+2q+8][n], B[kb+2q+9][n]}
// uint4 holds kki=0 (b0,b1) then kki=1 (b0,b1).
// ---------------------------------------------------------------------------
__global__ void w2frag_kernel(const float* __restrict__ W2) {
    const int n  = blockIdx.x * 256 + threadIdx.x;   // 0..1023
    const int ck = blockIdx.y;                       // 0..15 (32-K chunk)
    const int nt = n >> 7, wn = (n >> 6) & 1, j = (n >> 3) & 7, g = n & 7;
#pragma unroll
    for (int q = 0; q < 4; q++) {
        uint4 v;
        int k0 = ck * 32 + 2 * q;
        v.x = packbf(W2[(size_t)k0 * Vn + n],        W2[(size_t)(k0 + 1) * Vn + n]);
        v.y = packbf(W2[(size_t)(k0 + 8) * Vn + n],  W2[(size_t)(k0 + 9) * Vn + n]);
        v.z = packbf(W2[(size_t)(k0 + 16) * Vn + n], W2[(size_t)(k0 + 17) * Vn + n]);
        v.w = packbf(W2[(size_t)(k0 + 24) * Vn + n], W2[(size_t)(k0 + 25) * Vn + n]);
        g_W2f[(size_t)(ck * 8 + nt) * 512 + (wn * 8 + j) * 32 + 4 * g + q] = v;
    }
}

// ---------------------------------------------------------------------------
// Layer-1 projection, split over (row-tile 8, h-tile 128): 768 blocks.
// ---------------------------------------------------------------------------
__global__ __launch_bounds__(256)
void proj_kernel(const float* __restrict__ src, const float* __restrict__ tgt,
                 const float* __restrict__ W1, const float* __restrict__ b1) {
    __shared__ float se[8][Fn];
    const int rt = blockIdx.x;
    const bool isP = rt < 128;
    const float* enc = isP ? src : tgt;
    float* dst = isP ? g_P : g_Q;
    const float* Wp = isP ? W1 : (W1 + Fn * Hn);
    const int row0 = (isP ? rt : rt - 128) * 8;

    const int tid = threadIdx.x;
    for (int i = tid; i < 8 * Fn; i += 256)
        se[i >> 8][i & 255] = enc[(size_t)row0 * Fn + i];
    __syncthreads();

    const int h  = blockIdx.y * 128 + (tid & 127);
    const int rh = tid >> 7;               // 0..1 -> 4-row half

    float acc[4] = {0.f, 0.f, 0.f, 0.f};
    const float* w = Wp + h;
    for (int f = 0; f < Fn; f++) {
        float wv = w[(size_t)f * Hn];
#pragma unroll
        for (int r = 0; r < 4; r++)
            acc[r] = fmaf(se[rh * 4 + r][f], wv, acc[r]);
    }
    const float bias = isP ? b1[h] : 0.f;
#pragma unroll
    for (int r = 0; r < 4; r++)
        dst[(size_t)(row0 + rh * 4 + r) * Hn + h] = acc[r] + bias;
}

// ---------------------------------------------------------------------------
// Main GEMM: L[bt*128+s][n0+n] = sum_k relu(P[bt][k]+Q[b][s][k])*W2[k][n]
// BM=128 BN=128 BK=32, mma.m16n8k16 bf16. 8 warps 4x2 (warp tile 32x64).
// A built in fragment layout from gmem Q + sP; B pre-packed uint4 fragments.
// Output: fp16 raw logits into g_L.
// ---------------------------------------------------------------------------
constexpr int A_ENTRY = 528;                  // 512B fragment block + 16B pad

__global__ __launch_bounds__(256, 2)
void joint_gemm() {
    __shared__ char  As[2][16 * A_ENTRY];     // [buf][(wm*2+i)*2+kki] blocks
    __shared__ uint4 Bs[3][512];              // [stage][(wn*8+j)*32+lane]
    __shared__ float sP[Hn];

    const int bt  = blockIdx.y;               // b*T + t
    const int b   = bt >> 8;
    const int nt  = blockIdx.x;               // n-tile, n0 = nt*128
    const int tid = threadIdx.x;
    const int wid = tid >> 5;
    const int lane = tid & 31;

    const float* Qg = g_Q + (size_t)b * Sn * Hn;

    // builder decode: tid = wm[7:6] i[5] g[4:2] kki[1] qh[0]
    const int bm_wm = tid >> 6, bm_i = (tid >> 5) & 1;
    const int bm_g = (tid >> 2) & 7, bm_kki = (tid >> 1) & 1, bm_qh = tid & 1;
    const int bm_entry = ((bm_wm * 2 + bm_i) * 2 + bm_kki);
    const int bm_lt = 4 * bm_g + 2 * bm_qh;   // fragment lanes lt, lt+1
    const int s_lo = bm_wm * 32 + bm_i * 16 + bm_g;
    const int ka_  = bm_kki * 16 + bm_qh * 4; // k offset within 32-chunk
    const float* qlo_base = Qg + (size_t)s_lo * Hn + ka_;
    const float* qhi_base = qlo_base + 8 * Hn;

    float4 qv0, qv1, qv2, qv3;                // Q regs for next build
    auto ldq = [&](int k0n) {
        qv0 = *(const float4*)(qlo_base + k0n);
        qv1 = *(const float4*)(qlo_base + k0n + 8);
        qv2 = *(const float4*)(qhi_base + k0n);
        qv3 = *(const float4*)(qhi_base + k0n + 8);
    };

    auto buildA = [&](int buf, int k0n) {
        float4 pa = *(const float4*)(sP + k0n + ka_);
        float4 pb = *(const float4*)(sP + k0n + ka_ + 8);
        uint4* rowp = (uint4*)(As[buf] + bm_entry * A_ENTRY);
        uint4 u0, u1;
        u0.x = packbf(fmaxf(qv0.x + pa.x, 0.f), fmaxf(qv0.y + pa.y, 0.f));
        u0.y = packbf(fmaxf(qv2.x + pa.x, 0.f), fmaxf(qv2.y + pa.y, 0.f));
        u0.z = packbf(fmaxf(qv1.x + pb.x, 0.f), fmaxf(qv1.y + pb.y, 0.f));
        u0.w = packbf(fmaxf(qv3.x + pb.x, 0.f), fmaxf(qv3.y + pb.y, 0.f));
        u1.x = packbf(fmaxf(qv0.z + pa.z, 0.f), fmaxf(qv0.w + pa.w, 0.f));
        u1.y = packbf(fmaxf(qv2.z + pa.z, 0.f), fmaxf(qv2.w + pa.w, 0.f));
        u1.z = packbf(fmaxf(qv1.z + pb.z, 0.f), fmaxf(qv1.w + pb.w, 0.f));
        u1.w = packbf(fmaxf(qv3.z + pb.z, 0.f), fmaxf(qv3.w + pb.w, 0.f));
        rowp[bm_lt]     = u0;
        rowp[bm_lt + 1] = u1;
    };

    auto stageB = [&](int ck, int buf) {
        const char* src = (const char*)(g_W2f + (size_t)(ck * 8 + nt) * 512);
        uint32_t dst = smem_u32(Bs[buf]);
#pragma unroll
        for (int r = 0; r < 2; r++) {
            int c = tid + 256 * r;            // 512 chunks of 16B
            cp16(dst + c * 16, src + c * 16);
        }
    };

    // ---- prologue ----
    stageB(0, 0); cp_commit();
    stageB(1, 1); cp_commit();
    if (tid < 128)
        ((float4*)sP)[tid] = *((const float4*)(g_P + (size_t)bt * Hn) + tid);
    __syncthreads();                          // sP visible for builds

    ldq(0);
    buildA(0, 0);                             // A(0) into buf 0
    ldq(32);                                  // Q for A(1), in flight

    float acc[2][8][4];
#pragma unroll
    for (int i = 0; i < 2; i++)
#pragma unroll
        for (int j = 0; j < 8; j++)
#pragma unroll
            for (int e = 0; e < 4; e++) acc[i][j][e] = 0.f;

    const int wm = wid & 3;                   // 32-row slice
    const int wn = wid >> 2;                  // 64-col slice

    // ---- main loop ----
    for (int it = 0; it < 16; it++) {
        cp_wait<1>();                         // B(it) arrived
        __syncthreads();                      // A(it) stores + B(it) visible

        // build next A first: STS drain overlaps this iter's MMA issue
        if (it < 15) buildA((it + 1) & 1, (it + 1) * 32);

        const char*  Ab = As[it & 1];
        const uint4* Bb = Bs[it % 3] + (wn * 8) * 32;

        uint32_t a00[4], a01[4], a10[4], a11[4];
        *(uint4*)a00 = ((const uint4*)(Ab + ((wm * 2 + 0) * 2 + 0) * A_ENTRY))[lane];
        *(uint4*)a01 = ((const uint4*)(Ab + ((wm * 2 + 0) * 2 + 1) * A_ENTRY))[lane];
        *(uint4*)a10 = ((const uint4*)(Ab + ((wm * 2 + 1) * 2 + 0) * A_ENTRY))[lane];
        *(uint4*)a11 = ((const uint4*)(Ab + ((wm * 2 + 1) * 2 + 1) * A_ENTRY))[lane];

#pragma unroll
        for (int j = 0; j < 8; j++) {
            uint4 bv = Bb[j * 32 + lane];
            mma_bf16(acc[0][j], a00, bv.x, bv.y);
            mma_bf16(acc[0][j], a01, bv.z, bv.w);
            mma_bf16(acc[1][j], a10, bv.x, bv.y);
            mma_bf16(acc[1][j], a11, bv.z, bv.w);
        }

        // tail: prefetch Q for iter it+2, stage B for iter it+2
        if (it < 14) {
            ldq((it + 2) * 32);
            stageB(it + 2, (it + 2) % 3);
        }
        cp_commit();                          // one group per iter (may be empty)
    }

    // ---- epilogue: fp16 raw logits to g_L ----
    const int gg = lane >> 2, tq = lane & 3;
    const size_t rowbase = (size_t)bt * Sn;
#pragma unroll
    for (int i = 0; i < 2; i++) {
        int r0 = wm * 32 + i * 16 + gg;
#pragma unroll
        for (int j = 0; j < 8; j++) {
            int col = nt * 128 + wn * 64 + 8 * j + 2 * tq;
            *(__half2*)(g_L + (rowbase + r0) * Vn + col) =
                __floats2half2_rn(acc[i][j][0], acc[i][j][1]);
            *(__half2*)(g_L + (rowbase + r0 + 8) * Vn + col) =
                __floats2half2_rn(acc[i][j][2], acc[i][j][3]);
        }
    }
}

// ---------------------------------------------------------------------------
// log_softmax: read fp16 logits from g_L, add b2, write fp32 to out.
// One warp per row; 32 values per lane.
// ---------------------------------------------------------------------------
__global__ __launch_bounds__(256)
void lsm_kernel(float* __restrict__ out, const float* __restrict__ b2) {
    const int row  = blockIdx.x * 8 + (threadIdx.x >> 5);
    const int lane = threadIdx.x & 31;

    const uint4* pL = (const uint4*)(g_L + (size_t)row * Vn);  // 8 halves each
    const float4* pb = (const float4*)b2;

    float v[32];
    float mx = -1e30f;
#pragma unroll
    for (int i = 0; i < 4; i++) {
        uint4 u = pL[lane + 32 * i];
        int c4 = (lane + 32 * i) * 2;          // float4 index into b2
        float4 b0 = __ldg(&pb[c4]);
        float4 b1 = __ldg(&pb[c4 + 1]);
        float2 f0 = __half22float2(*(__half2*)&u.x);
        float2 f1 = __half22float2(*(__half2*)&u.y);
        float2 f2 = __half22float2(*(__half2*)&u.z);
        float2 f3 = __half22float2(*(__half2*)&u.w);
        float* vv = v + 8 * i;
        vv[0] = f0.x + b0.x; vv[1] = f0.y + b0.y;
        vv[2] = f1.x + b0.z; vv[3] = f1.y + b0.w;
        vv[4] = f2.x + b1.x; vv[5] = f2.y + b1.y;
        vv[6] = f3.x + b1.z; vv[7] = f3.y + b1.w;
#pragma unroll
        for (int e = 0; e < 8; e++) mx = fmaxf(mx, vv[e]);
    }
#pragma unroll
    for (int o = 16; o > 0; o >>= 1)
        mx = fmaxf(mx, __shfl_xor_sync(0xffffffffu, mx, o));

    float sum = 0.f;
#pragma unroll
    for (int e = 0; e < 32; e++) sum += __expf(v[e] - mx);
#pragma unroll
    for (int o = 16; o > 0; o >>= 1)
        sum += __shfl_xor_sync(0xffffffffu, sum, o);

    const float lse = mx + logf(sum);
    float4* po = (float4*)(out + (size_t)row * Vn);
#pragma unroll
    for (int i = 0; i < 4; i++) {
        const float* vv = v + 8 * i;
        po[(lane + 32 * i) * 2] =
            make_float4(vv[0] - lse, vv[1] - lse, vv[2] - lse, vv[3] - lse);
        po[(lane + 32 * i) * 2 + 1] =
            make_float4(vv[4] - lse, vv[5] - lse, vv[6] - lse, vv[7] - lse);
    }
}

// ---------------------------------------------------------------------------
extern "C" void kernel_launch(void* const* d_in, const int* in_sizes, int n_in,
                              void* d_out, int out_size) {
    const float* src = (const float*)d_in[0];  // [B,T,F]
    const float* tgt = (const float*)d_in[1];  // [B,S,F]
    const float* W1  = (const float*)d_in[2];  // [2F,H]
    const float* b1  = (const float*)d_in[3];  // [H]
    const float* W2  = (const float*)d_in[4];  // [H,V]
    const float* b2  = (const float*)d_in[5];  // [V]
    float* out = (float*)d_out;                // [B,T,S,V]

    (void)in_sizes; (void)n_in; (void)out_size;

    w2frag_kernel<<<dim3(4, 16), 256>>>(W2);
    proj_kernel<<<dim3(192, 4), 256>>>(src, tgt, W1, b1);

    joint_gemm<<<dim3(Vn / 128, Bn * Tn), 256>>>();

    lsm_kernel<<<(Bn * Tn * Sn) / 8, 256>>>(out, b2);
}

// round 8
// speedup vs baseline: 4.0266x; 1.2350x over previous
#include <cuda_runtime.h>
#include <cuda_bf16.h>
#include <cuda_fp16.h>
#include <cstdint>

// Problem constants
constexpr int Bn = 4, Tn = 256, Sn = 128, Fn = 256, Hn = 512, Vn = 1024;

// Scratch (allocation-free rule: __device__ globals)
__device__ float g_P[Bn * Tn * Hn];       // [b*T+t][h], includes b1
__device__ float g_Q[Bn * Sn * Hn];       // [b*S+s][h]
// W2 bf16 fragment order: [ck(16)][ntile(8)] x 512 uint4
__device__ uint4 g_W2f[16 * 8 * 512];
// A bf16 fragment order: [bt(1024)][ck(16)] x 512 uint4  (128 MB)
__device__ uint4 g_Af[(size_t)1024 * 16 * 512];
// fp16 raw logits scratch (256 MB)
__device__ __half g_L[(size_t)Bn * Tn * Sn * Vn];

// ---------------------------------------------------------------------------
// helpers
// ---------------------------------------------------------------------------
__device__ __forceinline__ uint32_t packbf(float lo, float hi) {
    __nv_bfloat162 h = __floats2bfloat162_rn(lo, hi);   // lo -> low 16 bits
    return *reinterpret_cast<uint32_t*>(&h);
}

__device__ __forceinline__ uint32_t smem_u32(const void* p) {
    uint32_t a;
    asm("{ .reg .u64 t; cvta.to.shared.u64 t, %1; cvt.u32.u64 %0, t; }"
        : "=r"(a) : "l"(p));
    return a;
}

__device__ __forceinline__ void cp16(uint32_t smem_dst, const void* gmem_src) {
    asm volatile("cp.async.cg.shared.global [%0], [%1], 16;"
                 :: "r"(smem_dst), "l"(gmem_src));
}
__device__ __forceinline__ void cp_commit() {
    asm volatile("cp.async.commit_group;");
}
template <int N>
__device__ __forceinline__ void cp_wait() {
    asm volatile("cp.async.wait_group %0;" :: "n"(N));
}

__device__ __forceinline__ void mma_bf16(float (&c)[4], const uint32_t (&a)[4],
                                         uint32_t b0, uint32_t b1) {
    asm volatile(
        "mma.sync.aligned.m16n8k16.row.col.f32.bf16.bf16.f32 "
        "{%0,%1,%2,%3}, {%4,%5,%6,%7}, {%8,%9}, {%0,%1,%2,%3};"
        : "+f"(c[0]), "+f"(c[1]), "+f"(c[2]), "+f"(c[3])
        : "r"(a[0]), "r"(a[1]), "r"(a[2]), "r"(a[3]), "r"(b0), "r"(b1));
}

// ---------------------------------------------------------------------------
// W2 [H][V] f32 -> g_W2f bf16 fragment order (one-time, 1MB out).
// ---------------------------------------------------------------------------
__global__ void w2frag_kernel(const float* __restrict__ W2) {
    const int n  = blockIdx.x * 256 + threadIdx.x;   // 0..1023
    const int ck = blockIdx.y;                       // 0..15 (32-K chunk)
    const int nt = n >> 7, wn = (n >> 6) & 1, j = (n >> 3) & 7, g = n & 7;
#pragma unroll
    for (int q = 0; q < 4; q++) {
        uint4 v;
        int k0 = ck * 32 + 2 * q;
        v.x = packbf(W2[(size_t)k0 * Vn + n],        W2[(size_t)(k0 + 1) * Vn + n]);
        v.y = packbf(W2[(size_t)(k0 + 8) * Vn + n],  W2[(size_t)(k0 + 9) * Vn + n]);
        v.z = packbf(W2[(size_t)(k0 + 16) * Vn + n], W2[(size_t)(k0 + 17) * Vn + n]);
        v.w = packbf(W2[(size_t)(k0 + 24) * Vn + n], W2[(size_t)(k0 + 25) * Vn + n]);
        g_W2f[(size_t)(ck * 8 + nt) * 512 + (wn * 8 + j) * 32 + 4 * g + q] = v;
    }
}

// ---------------------------------------------------------------------------
// Layer-1 projection, split over (row-tile 8, h-tile 128): 768 blocks.
// ---------------------------------------------------------------------------
__global__ __launch_bounds__(256)
void proj_kernel(const float* __restrict__ src, const float* __restrict__ tgt,
                 const float* __restrict__ W1, const float* __restrict__ b1) {
    __shared__ float se[8][Fn];
    const int rt = blockIdx.x;
    const bool isP = rt < 128;
    const float* enc = isP ? src : tgt;
    float* dst = isP ? g_P : g_Q;
    const float* Wp = isP ? W1 : (W1 + Fn * Hn);
    const int row0 = (isP ? rt : rt - 128) * 8;

    const int tid = threadIdx.x;
    for (int i = tid; i < 8 * Fn; i += 256)
        se[i >> 8][i & 255] = enc[(size_t)row0 * Fn + i];
    __syncthreads();

    const int h  = blockIdx.y * 128 + (tid & 127);
    const int rh = tid >> 7;               // 0..1 -> 4-row half

    float acc[4] = {0.f, 0.f, 0.f, 0.f};
    const float* w = Wp + h;
    for (int f = 0; f < Fn; f++) {
        float wv = w[(size_t)f * Hn];
#pragma unroll
        for (int r = 0; r < 4; r++)
            acc[r] = fmaf(se[rh * 4 + r][f], wv, acc[r]);
    }
    const float bias = isP ? b1[h] : 0.f;
#pragma unroll
    for (int r = 0; r < 4; r++)
        dst[(size_t)(row0 + rh * 4 + r) * Hn + h] = acc[r] + bias;
}

// ---------------------------------------------------------------------------
// A-fragment materializer: for each bt, write relu(P[bt]+Q[b]) as bf16
// m16n8k16 A row-major fragments. One block per bt, 16 K-chunks.
// Entry (mtile 0..7, kki 0..1) = 32 uint4; per (bt,ck): 16 entries = 8 KB.
// ---------------------------------------------------------------------------
__global__ __launch_bounds__(256)
void afrag_kernel() {
    __shared__ float sP[Hn];
    const int bt  = blockIdx.x;
    const int b   = bt >> 8;
    const int tid = threadIdx.x;

    if (tid < 128)
        ((float4*)sP)[tid] = *((const float4*)(g_P + (size_t)bt * Hn) + tid);
    __syncthreads();

    // decode: tid = wm[7:6] i[5] g[4:2] kki[1] qh[0]
    const int wm = tid >> 6, ii = (tid >> 5) & 1;
    const int g = (tid >> 2) & 7, kki = (tid >> 1) & 1, qh = tid & 1;
    const int mtile = wm * 2 + ii;
    const int entry = mtile * 2 + kki;
    const int lt = 4 * g + 2 * qh;            // fragment lanes lt, lt+1
    const int s_lo = mtile * 16 + g;
    const int ka_ = kki * 16 + qh * 4;        // k offset within 32-chunk
    const float* qlo = g_Q + (size_t)b * Sn * Hn + (size_t)s_lo * Hn + ka_;
    const float* qhi = qlo + 8 * Hn;
    uint4* dst = g_Af + (size_t)bt * 8192 + entry * 32;

    float4 qv0 = *(const float4*)(qlo);
    float4 qv1 = *(const float4*)(qlo + 8);
    float4 qv2 = *(const float4*)(qhi);
    float4 qv3 = *(const float4*)(qhi + 8);

    for (int ck = 0; ck < 16; ck++) {
        const int k0 = ck * 32;
        float4 pa = *(const float4*)(sP + k0 + ka_);
        float4 pb = *(const float4*)(sP + k0 + ka_ + 8);
        uint4 u0, u1;
        u0.x = packbf(fmaxf(qv0.x + pa.x, 0.f), fmaxf(qv0.y + pa.y, 0.f));
        u0.y = packbf(fmaxf(qv2.x + pa.x, 0.f), fmaxf(qv2.y + pa.y, 0.f));
        u0.z = packbf(fmaxf(qv1.x + pb.x, 0.f), fmaxf(qv1.y + pb.y, 0.f));
        u0.w = packbf(fmaxf(qv3.x + pb.x, 0.f), fmaxf(qv3.y + pb.y, 0.f));
        u1.x = packbf(fmaxf(qv0.z + pa.z, 0.f), fmaxf(qv0.w + pa.w, 0.f));
        u1.y = packbf(fmaxf(qv2.z + pa.z, 0.f), fmaxf(qv2.w + pa.w, 0.f));
        u1.z = packbf(fmaxf(qv1.z + pb.z, 0.f), fmaxf(qv1.w + pb.w, 0.f));
        u1.w = packbf(fmaxf(qv3.z + pb.z, 0.f), fmaxf(qv3.w + pb.w, 0.f));
        if (ck < 15) {                        // prefetch next Q chunk
            qv0 = *(const float4*)(qlo + k0 + 32);
            qv1 = *(const float4*)(qlo + k0 + 40);
            qv2 = *(const float4*)(qhi + k0 + 32);
            qv3 = *(const float4*)(qhi + k0 + 40);
        }
        dst[lt]     = u0;
        dst[lt + 1] = u1;
        dst += 512;                           // next ck
    }
}

// ---------------------------------------------------------------------------
// Main GEMM: pure fragment streaming. BM=128 BN=128 BK=32, m16n8k16 bf16.
// 4-stage cp.async pipeline; stage = A frags (8KB) + B frags (8KB).
// 8 warps 4x2 (warp tile 32x64). fp16 raw logits to g_L.
// ---------------------------------------------------------------------------
constexpr int STAGES = 4;
constexpr uint32_t STAGE_U4 = 1024;           // uint4 per stage (A 512 + B 512)
constexpr uint32_t SMEM_DYN = STAGES * STAGE_U4 * 16;   // 65536 B

__global__ __launch_bounds__(256, 2)
void joint_gemm() {
    extern __shared__ uint4 sm4[];

    const int bt  = blockIdx.y;               // b*T + t
    const int nt  = blockIdx.x;               // n-tile, n0 = nt*128
    const int tid = threadIdx.x;
    const int wid = tid >> 5;
    const int lane = tid & 31;
    const int wm = wid & 3;                   // 32-row slice
    const int wn = wid >> 2;                  // 64-col slice

    const uint4* Asrc = g_Af + (size_t)bt * 8192;         // +ck*512
    const uint4* Bsrc = g_W2f + (size_t)nt * 512;         // +ck*8*512

    auto issue = [&](int s) {
        uint32_t dst = smem_u32(sm4 + (s & (STAGES - 1)) * STAGE_U4);
        const char* as = (const char*)(Asrc + s * 512);
        const char* bs = (const char*)(Bsrc + (size_t)s * 8 * 512);
#pragma unroll
        for (int r = 0; r < 2; r++) {
            int c = tid + 256 * r;            // 0..511
            cp16(dst + c * 16, as + c * 16);
            cp16(dst + 8192 + c * 16, bs + c * 16);
        }
        cp_commit();
    };

    issue(0); issue(1); issue(2);

    float acc[2][8][4];
#pragma unroll
    for (int i = 0; i < 2; i++)
#pragma unroll
        for (int j = 0; j < 8; j++)
#pragma unroll
            for (int e = 0; e < 4; e++) acc[i][j][e] = 0.f;

    for (int it = 0; it < 16; it++) {
        cp_wait<2>();                         // stage it resident
        __syncthreads();

        const uint4* Ab = sm4 + (it & (STAGES - 1)) * STAGE_U4;
        const uint4* Bb = Ab + 512 + (wn * 8) * 32;

        uint32_t a00[4], a01[4], a10[4], a11[4];
        *(uint4*)a00 = Ab[((wm * 2 + 0) * 2 + 0) * 32 + lane];
        *(uint4*)a01 = Ab[((wm * 2 + 0) * 2 + 1) * 32 + lane];
        *(uint4*)a10 = Ab[((wm * 2 + 1) * 2 + 0) * 32 + lane];
        *(uint4*)a11 = Ab[((wm * 2 + 1) * 2 + 1) * 32 + lane];

#pragma unroll
        for (int j = 0; j < 8; j++) {
            uint4 bv = Bb[j * 32 + lane];
            mma_bf16(acc[0][j], a00, bv.x, bv.y);
            mma_bf16(acc[0][j], a01, bv.z, bv.w);
            mma_bf16(acc[1][j], a10, bv.x, bv.y);
            mma_bf16(acc[1][j], a11, bv.z, bv.w);
        }

        if (it < 13) issue(it + 3);
        else cp_commit();                     // keep one group per iter
    }

    // ---- epilogue: fp16 raw logits to g_L (streaming stores) ----
    const int gg = lane >> 2, tq = lane & 3;
    const size_t rowbase = (size_t)bt * Sn;
#pragma unroll
    for (int i = 0; i < 2; i++) {
        int r0 = wm * 32 + i * 16 + gg;
#pragma unroll
        for (int j = 0; j < 8; j++) {
            int col = nt * 128 + wn * 64 + 8 * j + 2 * tq;
            __half2 v0 = __floats2half2_rn(acc[i][j][0], acc[i][j][1]);
            __half2 v1 = __floats2half2_rn(acc[i][j][2], acc[i][j][3]);
            __stcs((__half2*)(g_L + (rowbase + r0) * Vn + col), v0);
            __stcs((__half2*)(g_L + (rowbase + r0 + 8) * Vn + col), v1);
        }
    }
}

// ---------------------------------------------------------------------------
// log_softmax: read fp16 logits from g_L (streaming), add b2, write fp32 out.
// One warp per row; 32 values per lane.
// ---------------------------------------------------------------------------
__global__ __launch_bounds__(256)
void lsm_kernel(float* __restrict__ out, const float* __restrict__ b2) {
    const int row  = blockIdx.x * 8 + (threadIdx.x >> 5);
    const int lane = threadIdx.x & 31;

    const uint4* pL = (const uint4*)(g_L + (size_t)row * Vn);  // 8 halves each
    const float4* pb = (const float4*)b2;

    float v[32];
    float mx = -1e30f;
#pragma unroll
    for (int i = 0; i < 4; i++) {
        uint4 u = __ldcs(&pL[lane + 32 * i]);
        int c4 = (lane + 32 * i) * 2;          // float4 index into b2
        float4 b0 = __ldg(&pb[c4]);
        float4 b1 = __ldg(&pb[c4 + 1]);
        float2 f0 = __half22float2(*(__half2*)&u.x);
        float2 f1 = __half22float2(*(__half2*)&u.y);
        float2 f2 = __half22float2(*(__half2*)&u.z);
        float2 f3 = __half22float2(*(__half2*)&u.w);
        float* vv = v + 8 * i;
        vv[0] = f0.x + b0.x; vv[1] = f0.y + b0.y;
        vv[2] = f1.x + b0.z; vv[3] = f1.y + b0.w;
        vv[4] = f2.x + b1.x; vv[5] = f2.y + b1.y;
        vv[6] = f3.x + b1.z; vv[7] = f3.y + b1.w;
#pragma unroll
        for (int e = 0; e < 8; e++) mx = fmaxf(mx, vv[e]);
    }
#pragma unroll
    for (int o = 16; o > 0; o >>= 1)
        mx = fmaxf(mx, __shfl_xor_sync(0xffffffffu, mx, o));

    float sum = 0.f;
#pragma unroll
    for (int e = 0; e < 32; e++) sum += __expf(v[e] - mx);
#pragma unroll
    for (int o = 16; o > 0; o >>= 1)
        sum += __shfl_xor_sync(0xffffffffu, sum, o);

    const float lse = mx + logf(sum);
    float4* po = (float4*)(out + (size_t)row * Vn);
#pragma unroll
    for (int i = 0; i < 4; i++) {
        const float* vv = v + 8 * i;
        __stcs(&po[(lane + 32 * i) * 2],
               make_float4(vv[0] - lse, vv[1] - lse, vv[2] - lse, vv[3] - lse));
        __stcs(&po[(lane + 32 * i) * 2 + 1],
               make_float4(vv[4] - lse, vv[5] - lse, vv[6] - lse, vv[7] - lse));
    }
}

// ---------------------------------------------------------------------------
extern "C" void kernel_launch(void* const* d_in, const int* in_sizes, int n_in,
                              void* d_out, int out_size) {
    const float* src = (const float*)d_in[0];  // [B,T,F]
    const float* tgt = (const float*)d_in[1];  // [B,S,F]
    const float* W1  = (const float*)d_in[2];  // [2F,H]
    const float* b1  = (const float*)d_in[3];  // [H]
    const float* W2  = (const float*)d_in[4];  // [H,V]
    const float* b2  = (const float*)d_in[5];  // [V]
    float* out = (float*)d_out;                // [B,T,S,V]

    (void)in_sizes; (void)n_in; (void)out_size;

    cudaFuncSetAttribute(joint_gemm,
                         cudaFuncAttributeMaxDynamicSharedMemorySize, SMEM_DYN);

    w2frag_kernel<<<dim3(4, 16), 256>>>(W2);
    proj_kernel<<<dim3(192, 4), 256>>>(src, tgt, W1, b1);
    afrag_kernel<<<1024, 256>>>();

    joint_gemm<<<dim3(Vn / 128, Bn * Tn), 256, SMEM_DYN>>>();

    lsm_kernel<<<(Bn * Tn * Sn) / 8, 256>>>(out, b2);
}